// round 15
// baseline (speedup 1.0000x reference)
#include <cuda_runtime.h>
#include <cuda_fp16.h>
#include <math.h>
#include <cstdint>

#define LN_EPS 1e-5f
#define NEG_FILL -1.0e9f
#define MAXB 8192

// ---------------- device scratch ----------------
__device__ unsigned g_gf_enc[MAXB * 128];
__device__ float    g_score[MAXB];
__device__ float    g_ln1[44];   // closed-form LN(64) coefficients
__device__ float    g_sum;      // sum of |score| (accumulated by k_dec)
__device__ unsigned g_ticket;   // k_dec completion ticket

// ---------------- helpers ----------------
__device__ __forceinline__ unsigned enc_f(float f) {
    int i = __float_as_int(f);
    unsigned u = (unsigned)i;
    return (i < 0) ? ~u : (u | 0x80000000u);
}
__device__ __forceinline__ float dec_f(unsigned u) {
    return (u & 0x80000000u) ? __int_as_float((int)(u & 0x7FFFFFFFu))
                             : __int_as_float((int)(~u));
}
__device__ __forceinline__ float lrelu(float v) { return v >= 0.0f ? v : 0.2f * v; }
__device__ __forceinline__ uint32_t smem_u32(const void* p) {
    return (uint32_t)__cvta_generic_to_shared(p);
}
__device__ __forceinline__ void cp_async16(uint32_t dst, const void* src, bool full) {
    int sz = full ? 16 : 0;
    asm volatile("cp.async.cg.shared.global [%0], [%1], 16, %2;"
                 :: "r"(dst), "l"(src), "r"(sz));
}
#define CP_COMMIT() asm volatile("cp.async.commit_group;" ::: "memory")
#define CP_WAIT0()  asm volatile("cp.async.wait_group 0;" ::: "memory")

// fp16 warp MMA: D(16x8,f32) += A(16x16,f16) * B(16x8,f16)
__device__ __forceinline__ void mma_f16(float& c0, float& c1, float& c2, float& c3,
                                        uint32_t a0, uint32_t a1, uint32_t a2, uint32_t a3,
                                        uint32_t b0, uint32_t b1) {
    asm volatile(
        "mma.sync.aligned.m16n8k16.row.col.f32.f16.f16.f32 "
        "{%0,%1,%2,%3}, {%4,%5,%6,%7}, {%8,%9}, {%0,%1,%2,%3};"
        : "+f"(c0), "+f"(c1), "+f"(c2), "+f"(c3)
        : "r"(a0), "r"(a1), "r"(a2), "r"(a3), "r"(b0), "r"(b1));
}

// k-pair permuted half index (LDS.64 -> fragment pairs)
__device__ __host__ __forceinline__ int sidx16(int k) {
    return ((k >> 4) << 4) | ((((k >> 1) & 3) << 2) | (((k >> 3) & 1) << 1) | (k & 1));
}

// ---------------- kernel A: init pooled buffer + LN coefficients ----------------
__global__ void k_init(int n, const float* __restrict__ w1, const float* __restrict__ b1) {
    int i = blockIdx.x * blockDim.x + threadIdx.x;
    if (i < n) g_gf_enc[i] = enc_f(NEG_FILL);
    if (blockIdx.x == 0 && threadIdx.x == 0) { g_sum = 0.f; g_ticket = 0u; }
    if (blockIdx.x == 0 && threadIdx.x < 44) {
        int t = threadIdx.x;
        float v = 0.f;
        if (t < 28) {
            int j = 0, k = 0, idx = t;
            #pragma unroll 1
            for (j = 0; j < 7; j++) { int len = 7 - j; if (idx < len) { k = j + idx; break; } idx -= len; }
            float s = 0.f;
            for (int e = 0; e < 64; e++) s = fmaf(w1[j*64+e], w1[k*64+e], s);
            v = (j == k) ? s : 2.0f * s;
        } else if (t < 35) {
            int j = t - 28;
            float s = 0.f;
            for (int e = 0; e < 64; e++) s = fmaf(b1[e], w1[j*64+e], s);
            v = 2.0f * s;
        } else if (t < 42) {
            int j = t - 35;
            float s = 0.f;
            for (int e = 0; e < 64; e++) s += w1[j*64+e];
            v = s * (1.0f/64.0f);
        } else if (t == 42) {
            float s = 0.f;
            for (int e = 0; e < 64; e++) s += b1[e];
            v = s * (1.0f/64.0f);
        } else {
            float s = 0.f;
            for (int e = 0; e < 64; e++) s = fmaf(b1[e], b1[e], s);
            v = s;
        }
        g_ln1[t] = v;
    }
}

// ---------------- k_main layout (R11 champion, unchanged) ----------------
#define TB 256
#define ROWS 128
#define AP_H 80              // halves per row; conflict-free fragment LDS.64
#define OFF_B    20480                 // A: 128*80*2
#define OFF_PARM (20480 + 20480)       // B: 128*80*2
#define PF_SBI   640
#define PF_XS    896
#define PF_CS    1664
#define SMEM_NEED (OFF_PARM + 2688 * 4)

__global__ __launch_bounds__(256, 2) void k_main(
    const float* __restrict__ muons, const int* __restrict__ bidx,
    const float* __restrict__ cond,
    const float* __restrict__ w1, const float* __restrict__ b1,
    const float* __restrict__ g1, const float* __restrict__ be1,
    const float* __restrict__ w2, const float* __restrict__ b2,
    const float* __restrict__ g2, const float* __restrict__ be2,
    int N, int nTiles)
{
    extern __shared__ char base[];
    __half* const Ah   = (__half*)(base);            // A operand (f16, k-permuted)
    __half* const Bh   = (__half*)(base + OFF_B);    // B operand (f16, k-permuted)
    float*  const PR   = (float*)(base + OFF_PARM);
    float* const B2s  = PR;            // 128
    float* const G2s  = B2s + 128;     // 128
    float* const BE2s = G2s + 128;     // 128
    float* const LNC  = BE2s + 128;    // 44 (+pad to 640)
    int*   const SBIb = (int*)(PR + PF_SBI);
    float* const Xsb  = PR + PF_XS;
    float* const Csb  = PR + PF_CS;

    const int tid  = threadIdx.x;
    const int lane = tid & 31;
    const int wrp  = tid >> 5;
    const int quad = lane >> 2;
    const int tig  = lane & 3;
    const int s16  = sidx16(lane);
    const int lr0  = wrp * 16;

    int*   const SBw = SBIb + wrp * 32;
    float* const Xw  = Xsb  + wrp * 96;
    float* const Cw  = Csb  + wrp * 128;
    const uint32_t xw_base  = smem_u32(Xw);
    const uint32_t sbw_base = smem_u32(SBw);

    // ---- per-lane constant layer1 params ----
    float w1a[7], w1b[7];
    #pragma unroll
    for (int j = 0; j < 7; j++) { w1a[j] = w1[j*64 + lane]; w1b[j] = w1[j*64 + lane + 32]; }
    const float b1a = b1[lane], b1b = b1[lane + 32];
    const float g1a = g1[lane], g1b = g1[lane + 32];
    const float e1a = be1[lane], e1b = be1[lane + 32];

    // ---- one-time smem: layer2 params + LN coeffs + B operand ----
    for (int i = tid; i < 128; i += TB) { B2s[i] = b2[i]; G2s[i] = g2[i]; BE2s[i] = be2[i]; }
    if (tid < 44) LNC[tid] = g_ln1[tid];
    for (int i = tid; i < 8192; i += TB) {
        int n = i & 127, k = i >> 7;
        Bh[n * AP_H + sidx16(k)] = __float2half_rn(w2[k * 128 + n]);
    }
    __syncthreads();

    // ---- per-warp prologue: fetch tile0's X/SB, gather cond ----
    {
        int rg = blockIdx.x * ROWS + lr0;
        if (lane < 12) {
            int gi = rg * 3 + lane * 4;
            cp_async16(xw_base + lane * 16, muons + gi, gi + 4 <= 3 * N);
        } else if (lane < 16) {
            int gi = rg + (lane - 12) * 4;
            cp_async16(sbw_base + (lane - 12) * 16, bidx + gi, gi + 4 <= N);
        }
        CP_COMMIT(); CP_WAIT0(); __syncwarp();
        if (lane < 16) {
            int r = rg + lane;
            int bi = (r < N) ? SBw[lane] : -1;
            SBw[lane] = bi;
            float4 c4 = (bi >= 0) ? *(const float4*)(cond + 4 * bi)
                                  : make_float4(0.f, 0.f, 0.f, 0.f);
            *(float4*)(Cw + lane * 4) = c4;
        }
        __syncwarp();
    }

    int it = 0;
    for (int tile = blockIdx.x; tile < nTiles; tile += gridDim.x, it ^= 1) {
        const int bufc = it, bufn = it ^ 1;
        const float* Xc  = Xw + bufc * 48;
        const float* Cc  = Cw + bufc * 64;
        const int*   SBc = SBw + bufc * 16;
        int*         SBn = SBw + bufn * 16;
        float*       Cn  = Cw + bufn * 64;

        const int  tnxt   = tile + gridDim.x;
        const bool vn     = tnxt < nTiles;
        const int  rg2    = tnxt * ROWS + lr0;

        // ---- per-warp prefetch of next tile's X/SB ----
        if (vn) {
            if (lane < 12) {
                int gi = rg2 * 3 + lane * 4;
                cp_async16(xw_base + (bufn * 48) * 4 + lane * 16, muons + gi, gi + 4 <= 3 * N);
            } else if (lane < 16) {
                int gi = rg2 + (lane - 12) * 4;
                cp_async16(sbw_base + (bufn * 16) * 4 + (lane - 12) * 16, bidx + gi, gi + 4 <= N);
            }
        }
        CP_COMMIT();

        // ---- event fast-path test ----
        const int ebi0  = SBc[0];
        const int ebi15 = SBc[15];
        const bool sfast = (ebi0 == ebi15) && (ebi0 >= 0);

        // ---- stage 1: layer1 (7->64) + closed-form LN(64) + lrelu -> A (f16) ----
        if (sfast) {
            const float4 cc = *(const float4*)(Cc);
            float base_a = b1a, base_b = b1b;
            base_a = fmaf(cc.x, w1a[3], base_a); base_b = fmaf(cc.x, w1b[3], base_b);
            base_a = fmaf(cc.y, w1a[4], base_a); base_b = fmaf(cc.y, w1b[4], base_b);
            base_a = fmaf(cc.z, w1a[5], base_a); base_b = fmaf(cc.z, w1b[5], base_b);
            base_a = fmaf(cc.w, w1a[6], base_a); base_b = fmaf(cc.w, w1b[6], base_b);
            float m_ev = LNC[42];
            m_ev = fmaf(cc.x, LNC[38], m_ev); m_ev = fmaf(cc.y, LNC[39], m_ev);
            m_ev = fmaf(cc.z, LNC[40], m_ev); m_ev = fmaf(cc.w, LNC[41], m_ev);
            const float mw0 = LNC[35], mw1 = LNC[36], mw2 = LNC[37];
            float l0 = LNC[28];
            l0 = fmaf(cc.x, LNC[3],  l0); l0 = fmaf(cc.y, LNC[4],  l0);
            l0 = fmaf(cc.z, LNC[5],  l0); l0 = fmaf(cc.w, LNC[6],  l0);
            float l1 = LNC[29];
            l1 = fmaf(cc.x, LNC[9],  l1); l1 = fmaf(cc.y, LNC[10], l1);
            l1 = fmaf(cc.z, LNC[11], l1); l1 = fmaf(cc.w, LNC[12], l1);
            float l2 = LNC[30];
            l2 = fmaf(cc.x, LNC[14], l2); l2 = fmaf(cc.y, LNC[15], l2);
            l2 = fmaf(cc.z, LNC[16], l2); l2 = fmaf(cc.w, LNC[17], l2);
            const float q00 = LNC[0], q01 = LNC[1], q02 = LNC[2];
            const float q11 = LNC[7], q12 = LNC[8], q22 = LNC[13];
            float q_ev = LNC[43];
            {
                float t3 = LNC[31];
                t3 = fmaf(cc.x, LNC[18], t3); t3 = fmaf(cc.y, LNC[19], t3);
                t3 = fmaf(cc.z, LNC[20], t3); t3 = fmaf(cc.w, LNC[21], t3);
                q_ev = fmaf(cc.x, t3, q_ev);
                float t4 = LNC[32];
                t4 = fmaf(cc.y, LNC[22], t4); t4 = fmaf(cc.z, LNC[23], t4);
                t4 = fmaf(cc.w, LNC[24], t4);
                q_ev = fmaf(cc.y, t4, q_ev);
                float t5 = LNC[33];
                t5 = fmaf(cc.z, LNC[25], t5); t5 = fmaf(cc.w, LNC[26], t5);
                q_ev = fmaf(cc.z, t5, q_ev);
                float t6 = fmaf(cc.w, LNC[27], LNC[34]);
                q_ev = fmaf(cc.w, t6, q_ev);
            }
            #pragma unroll 4
            for (int i = 0; i < 16; i++) {
                float x0 = Xc[i*3], x1 = Xc[i*3+1], x2 = Xc[i*3+2];
                float oa = fmaf(x2, w1a[2], fmaf(x1, w1a[1], fmaf(x0, w1a[0], base_a)));
                float ob = fmaf(x2, w1b[2], fmaf(x1, w1b[1], fmaf(x0, w1b[0], base_b)));
                float m  = fmaf(x2, mw2, fmaf(x1, mw1, fmaf(x0, mw0, m_ev)));
                float q  = q_ev;
                q = fmaf(x0, fmaf(x0, q00, l0), q);
                q = fmaf(x1, fmaf(x1, q11, fmaf(x0, q01, l1)), q);
                q = fmaf(x2, fmaf(x2, q22, fmaf(x1, q12, fmaf(x0, q02, l2))), q);
                float var  = fmaf(-m, m, q * (1.0f/64.0f));
                float rstd = rsqrtf(var + LN_EPS);
                float ha = lrelu(fmaf((oa - m) * rstd, g1a, e1a));
                float hb = lrelu(fmaf((ob - m) * rstd, g1b, e1b));
                Ah[(lr0 + i) * AP_H + s16]      = __float2half_rn(ha);
                Ah[(lr0 + i) * AP_H + s16 + 32] = __float2half_rn(hb);
            }
        } else {
            const int off7[7] = {0, 7, 13, 18, 22, 25, 27};
            #pragma unroll 2
            for (int i = 0; i < 16; i++) {
                float4 cc = *(const float4*)(Cc + i * 4);
                float z[7];
                z[0] = Xc[i*3]; z[1] = Xc[i*3+1]; z[2] = Xc[i*3+2];
                z[3] = cc.x; z[4] = cc.y; z[5] = cc.z; z[6] = cc.w;
                float oa = b1a, ob = b1b;
                #pragma unroll
                for (int j = 0; j < 7; j++) {
                    oa = fmaf(z[j], w1a[j], oa);
                    ob = fmaf(z[j], w1b[j], ob);
                }
                float m = LNC[42];
                #pragma unroll
                for (int j = 0; j < 7; j++) m = fmaf(z[j], LNC[35 + j], m);
                float q = LNC[43];
                #pragma unroll
                for (int j = 0; j < 7; j++) {
                    float t = LNC[28 + j];
                    #pragma unroll
                    for (int k = j; k < 7; k++) t = fmaf(z[k], LNC[off7[j] + k - j], t);
                    q = fmaf(z[j], t, q);
                }
                float var  = fmaf(-m, m, q * (1.0f/64.0f));
                float rstd = rsqrtf(var + LN_EPS);
                float ha = lrelu(fmaf((oa - m) * rstd, g1a, e1a));
                float hb = lrelu(fmaf((ob - m) * rstd, g1b, e1b));
                Ah[(lr0 + i) * AP_H + s16]      = __float2half_rn(ha);
                Ah[(lr0 + i) * AP_H + s16 + 32] = __float2half_rn(hb);
            }
        }
        __syncwarp();

        // ---- stage 2: GEMM 16x128x64 per warp via m16n8k16.f16 ----
        float acc[16][4];
        #pragma unroll
        for (int nt = 0; nt < 16; nt++)
            #pragma unroll
            for (int c = 0; c < 4; c++) acc[nt][c] = 0.f;

        const __half* ap0 = Ah + (lr0 + quad) * AP_H + tig * 4;
        const __half* ap1 = ap0 + 8 * AP_H;
        const __half* bp  = Bh + quad * AP_H + tig * 4;
        #pragma unroll
        for (int ks = 0; ks < 4; ks++) {
            uint2 A0 = *(const uint2*)(ap0 + ks * 16);
            uint2 A1 = *(const uint2*)(ap1 + ks * 16);
            #pragma unroll
            for (int nt = 0; nt < 16; nt++) {
                uint2 Bv = *(const uint2*)(bp + nt * 8 * AP_H + ks * 16);
                mma_f16(acc[nt][0], acc[nt][1], acc[nt][2], acc[nt][3],
                        A0.x, A1.x, A0.y, A1.y, Bv.x, Bv.y);
            }
        }

        // ---- wait prefetch; patch SB; launch next-tile cond gather ----
        CP_WAIT0(); __syncwarp();
        float4 c4n = make_float4(0.f, 0.f, 0.f, 0.f);
        int bin = -1;
        if (vn && lane < 16) {
            int r2 = rg2 + lane;
            bin = (r2 < N) ? SBn[lane] : -1;
            if (bin >= 0) c4n = *(const float4*)(cond + 4 * bin);
        }

        // ---- stage 3a: bias + LN(128) stats (quad-local) ----
        float sA = 0.f, qA = 0.f, sB = 0.f, qB = 0.f;
        #pragma unroll
        for (int nt = 0; nt < 16; nt++) {
            int col = nt * 8 + tig * 2;
            float2 bb = *(const float2*)(B2s + col);
            acc[nt][0] += bb.x; acc[nt][1] += bb.y;
            acc[nt][2] += bb.x; acc[nt][3] += bb.y;
            sA += acc[nt][0] + acc[nt][1];
            qA = fmaf(acc[nt][0], acc[nt][0], fmaf(acc[nt][1], acc[nt][1], qA));
            sB += acc[nt][2] + acc[nt][3];
            qB = fmaf(acc[nt][2], acc[nt][2], fmaf(acc[nt][3], acc[nt][3], qB));
        }
        #pragma unroll
        for (int d = 1; d <= 2; d <<= 1) {
            sA += __shfl_xor_sync(0xFFFFFFFFu, sA, d);
            qA += __shfl_xor_sync(0xFFFFFFFFu, qA, d);
            sB += __shfl_xor_sync(0xFFFFFFFFu, sB, d);
            qB += __shfl_xor_sync(0xFFFFFFFFu, qB, d);
        }
        float mA  = sA * (1.0f/128.0f);
        float rsA = rsqrtf(fmaf(-mA, mA, qA * (1.0f/128.0f)) + LN_EPS);
        float mB  = sB * (1.0f/128.0f);
        float rsB = rsqrtf(fmaf(-mB, mB, qB * (1.0f/128.0f)) + LN_EPS);

        // ---- stage 3b+3c: normalize + lrelu, pool + direct RED.MAX ----
        const int bi_ra = SBc[quad];
        const int bi_rb = SBc[quad + 8];
        unsigned* const gfast = g_gf_enc + (sfast ? ebi0 * 128 : 0);

        #pragma unroll
        for (int nt = 0; nt < 16; nt++) {
            int col = nt * 8 + tig * 2;
            float2 gg = *(const float2*)(G2s + col);
            float2 ee = *(const float2*)(BE2s + col);
            float v0 = lrelu(fmaf((acc[nt][0] - mA) * rsA, gg.x, ee.x));
            float v1 = lrelu(fmaf((acc[nt][1] - mA) * rsA, gg.y, ee.y));
            float v2 = lrelu(fmaf((acc[nt][2] - mB) * rsB, gg.x, ee.x));
            float v3 = lrelu(fmaf((acc[nt][3] - mB) * rsB, gg.y, ee.y));
            if (sfast) {
                float m0 = fmaxf(v0, v2), m1 = fmaxf(v1, v3);
                #pragma unroll
                for (int d = 4; d <= 16; d <<= 1) {
                    m0 = fmaxf(m0, __shfl_xor_sync(0xFFFFFFFFu, m0, d));
                    m1 = fmaxf(m1, __shfl_xor_sync(0xFFFFFFFFu, m1, d));
                }
                if (quad == (nt >> 1)) {
                    atomicMax(gfast + col,     enc_f(m0));
                    atomicMax(gfast + col + 1, enc_f(m1));
                }
            } else {
                if (bi_ra >= 0) {
                    atomicMax(&g_gf_enc[bi_ra * 128 + col],     enc_f(v0));
                    atomicMax(&g_gf_enc[bi_ra * 128 + col + 1], enc_f(v1));
                }
                if (bi_rb >= 0) {
                    atomicMax(&g_gf_enc[bi_rb * 128 + col],     enc_f(v2));
                    atomicMax(&g_gf_enc[bi_rb * 128 + col + 1], enc_f(v3));
                }
            }
        }

        if (vn && lane < 16) {
            SBn[lane] = bin;
            *(float4*)(Cn + lane * 4) = c4n;
        }
        __syncwarp();
    }
}

// ---------------- kernel C: decision net (4 rows/warp) + fused finalizer ----------------
__global__ __launch_bounds__(256) void k_dec(
    const float* __restrict__ cond,
    const float* __restrict__ w3, const float* __restrict__ b3,
    const float* __restrict__ g3, const float* __restrict__ be3,
    const float* __restrict__ w4, const float* __restrict__ b4,
    const float* __restrict__ g4, const float* __restrict__ be4,
    const float* __restrict__ w5, const float* __restrict__ b5,
    float* __restrict__ out, int B)
{
    extern __shared__ float sm[];
    float* W3 = sm;
    float* W4 = W3 + 16896;
    float* W5 = W4 + 8192;
    float* B3 = W5 + 64;
    float* G3 = B3 + 128;
    float* BE3= G3 + 128;
    float* B4 = BE3 + 128;
    float* G4 = B4 + 64;
    float* BE4= G4 + 64;
    float* XB = BE4 + 64;
    __shared__ int sIsLast;

    const int tid = threadIdx.x, lane = tid & 31, wrp = tid >> 5;
    for (int i = tid; i < 16896; i += 256) W3[i] = w3[i];
    for (int i = tid; i < 8192;  i += 256) W4[i] = w4[i];
    for (int i = tid; i < 64;    i += 256) { W5[i] = w5[i]; B4[i] = b4[i]; G4[i] = g4[i]; BE4[i] = be4[i]; }
    for (int i = tid; i < 128;   i += 256) { B3[i] = b3[i]; G3[i] = g3[i]; BE3[i] = be3[i]; }
    __syncthreads();

    float* xb = XB + wrp * 136;
    const float b5v = b5[0];
    float absacc = 0.f;

    #pragma unroll 1
    for (int i = 0; i < 4; i++) {
        int row = (blockIdx.x * 8 + wrp) * 4 + i;
        if (row >= B) break;
        __syncwarp();
        #pragma unroll
        for (int j = 0; j < 4; j++)
            xb[lane + 32*j] = dec_f(g_gf_enc[row*128 + lane + 32*j]);
        if (lane < 4) xb[128 + lane] = cond[row*4 + lane];
        __syncwarp();

        float a0 = B3[lane], a1 = B3[lane+32], a2 = B3[lane+64], a3 = B3[lane+96];
        #pragma unroll 4
        for (int k = 0; k < 132; k++) {
            float xk = xb[k];
            const float* wr = W3 + k*128;
            a0 = fmaf(xk, wr[lane],      a0);
            a1 = fmaf(xk, wr[lane+32],   a1);
            a2 = fmaf(xk, wr[lane+64],   a2);
            a3 = fmaf(xk, wr[lane+96],   a3);
        }
        float s = a0+a1+a2+a3;
        float q = a0*a0 + a1*a1 + a2*a2 + a3*a3;
        #pragma unroll
        for (int d = 16; d; d >>= 1) {
            s += __shfl_xor_sync(0xFFFFFFFFu, s, d);
            q += __shfl_xor_sync(0xFFFFFFFFu, q, d);
        }
        float m = s * (1.0f/128.0f);
        float var = fmaf(-m, m, q * (1.0f/128.0f));
        float rs = rsqrtf(var + LN_EPS);
        a0 = lrelu(fmaf((a0-m)*rs, G3[lane],    BE3[lane]));
        a1 = lrelu(fmaf((a1-m)*rs, G3[lane+32], BE3[lane+32]));
        a2 = lrelu(fmaf((a2-m)*rs, G3[lane+64], BE3[lane+64]));
        a3 = lrelu(fmaf((a3-m)*rs, G3[lane+96], BE3[lane+96]));
        __syncwarp();
        xb[lane] = a0; xb[lane+32] = a1; xb[lane+64] = a2; xb[lane+96] = a3;
        __syncwarp();

        float c0v = B4[lane], c1v = B4[lane+32];
        #pragma unroll 4
        for (int k = 0; k < 128; k++) {
            float xk = xb[k];
            c0v = fmaf(xk, W4[k*64 + lane],      c0v);
            c1v = fmaf(xk, W4[k*64 + lane + 32], c1v);
        }
        s = c0v + c1v;
        q = c0v*c0v + c1v*c1v;
        #pragma unroll
        for (int d = 16; d; d >>= 1) {
            s += __shfl_xor_sync(0xFFFFFFFFu, s, d);
            q += __shfl_xor_sync(0xFFFFFFFFu, q, d);
        }
        m = s * (1.0f/64.0f);
        var = fmaf(-m, m, q * (1.0f/64.0f));
        rs = rsqrtf(var + LN_EPS);
        c0v = lrelu(fmaf((c0v-m)*rs, G4[lane],    BE4[lane]));
        c1v = lrelu(fmaf((c1v-m)*rs, G4[lane+32], BE4[lane+32]));

        float p = c0v * W5[lane] + c1v * W5[lane+32];
        #pragma unroll
        for (int d = 16; d; d >>= 1) p += __shfl_xor_sync(0xFFFFFFFFu, p, d);
        if (lane == 0) {
            float sc = p + b5v;
            g_score[row] = sc;
            absacc += fabsf(sc);
        }
    }
    if (lane == 0 && absacc != 0.f) atomicAdd(&g_sum, absacc);

    // ---- last-block ticket: fused EMA normalize + tanh ----
    __syncthreads();
    if (tid == 0) {
        __threadfence();   // make this block's g_score/g_sum globally visible
        unsigned t = atomicAdd(&g_ticket, 1u);
        sIsLast = (t == gridDim.x - 1u) ? 1 : 0;
    }
    __syncthreads();
    if (sIsLast) {
        __threadfence();   // acquire all other blocks' stores
        float mean  = g_sum / (float)B;
        float ema   = 0.99f + 0.01f * mean;
        float denom = fmaxf(ema, 0.1f);
        for (int i = tid; i < B; i += 256) {
            float sc = g_score[i] / denom;
            sc = fminf(fmaxf(sc, -5.0f), 5.0f);
            out[i] = 10.0f * tanhf(sc * 0.2f);
        }
    }
}

// ---------------- launch ----------------
extern "C" void kernel_launch(void* const* d_in, const int* in_sizes, int n_in,
                              void* d_out, int out_size) {
    const float* muons = (const float*)d_in[0];
    const int*   bidx  = (const int*)  d_in[1];
    const float* cond  = (const float*)d_in[2];
    const float* w1  = (const float*)d_in[4];
    const float* b1  = (const float*)d_in[5];
    const float* g1  = (const float*)d_in[6];
    const float* be1 = (const float*)d_in[7];
    const float* w2  = (const float*)d_in[8];
    const float* b2  = (const float*)d_in[9];
    const float* g2  = (const float*)d_in[10];
    const float* be2 = (const float*)d_in[11];
    const float* w3  = (const float*)d_in[12];
    const float* b3  = (const float*)d_in[13];
    const float* g3  = (const float*)d_in[14];
    const float* be3 = (const float*)d_in[15];
    const float* w4  = (const float*)d_in[16];
    const float* b4  = (const float*)d_in[17];
    const float* g4  = (const float*)d_in[18];
    const float* be4 = (const float*)d_in[19];
    const float* w5  = (const float*)d_in[20];
    const float* b5  = (const float*)d_in[21];

    int N = in_sizes[0] / 3;
    int B = in_sizes[2] / 4;
    if (B > MAXB) B = MAXB;

    static const size_t SMEM_DEC = (size_t)(16896 + 8192 + 64 + 128*3 + 64*3 + 8*136) * 4;
    cudaFuncSetAttribute(k_main, cudaFuncAttributeMaxDynamicSharedMemorySize, (int)SMEM_NEED);
    cudaFuncSetAttribute(k_dec,  cudaFuncAttributeMaxDynamicSharedMemorySize, (int)SMEM_DEC);

    int initN = B * 128;
    k_init<<<(initN + 255) / 256, 256>>>(initN, w1, b1);

    int nTiles = (N + ROWS - 1) / ROWS;
    int nBlocks = 2 * 148;
    if (nBlocks > nTiles) nBlocks = nTiles;
    k_main<<<nBlocks, TB, SMEM_NEED>>>(muons, bidx, cond,
                                       w1, b1, g1, be1, w2, b2, g2, be2, N, nTiles);

    int decBlocks = (B + 31) / 32;
    k_dec<<<decBlocks, 256, SMEM_DEC>>>(cond, w3, b3, g3, be3,
                                        w4, b4, g4, be4, w5, b5,
                                        (float*)d_out, B);
}

// round 16
// speedup vs baseline: 1.0413x; 1.0413x over previous
#include <cuda_runtime.h>
#include <cuda_fp16.h>
#include <math.h>
#include <cstdint>

#define LN_EPS 1e-5f
#define NEG_FILL -1.0e9f
#define MAXB 8192

// ---------------- device scratch ----------------
__device__ unsigned g_gf_enc[MAXB * 128];
__device__ float    g_score[MAXB];
__device__ float    g_ln1[44];   // closed-form LN(64) coefficients
__device__ float    g_sum;       // sum of |score| (accumulated by k_dec)

// ---------------- helpers ----------------
__device__ __forceinline__ unsigned enc_f(float f) {
    int i = __float_as_int(f);
    unsigned u = (unsigned)i;
    return (i < 0) ? ~u : (u | 0x80000000u);
}
__device__ __forceinline__ float dec_f(unsigned u) {
    return (u & 0x80000000u) ? __int_as_float((int)(u & 0x7FFFFFFFu))
                             : __int_as_float((int)(~u));
}
__device__ __forceinline__ float lrelu(float v) { return v >= 0.0f ? v : 0.2f * v; }
__device__ __forceinline__ uint32_t smem_u32(const void* p) {
    return (uint32_t)__cvta_generic_to_shared(p);
}
__device__ __forceinline__ void cp_async16(uint32_t dst, const void* src, bool full) {
    int sz = full ? 16 : 0;
    asm volatile("cp.async.cg.shared.global [%0], [%1], 16, %2;"
                 :: "r"(dst), "l"(src), "r"(sz));
}
#define CP_COMMIT() asm volatile("cp.async.commit_group;" ::: "memory")
#define CP_WAIT0()  asm volatile("cp.async.wait_group 0;" ::: "memory")

// fp16 warp MMA: D(16x8,f32) += A(16x16,f16) * B(16x8,f16)
__device__ __forceinline__ void mma_f16(float& c0, float& c1, float& c2, float& c3,
                                        uint32_t a0, uint32_t a1, uint32_t a2, uint32_t a3,
                                        uint32_t b0, uint32_t b1) {
    asm volatile(
        "mma.sync.aligned.m16n8k16.row.col.f32.f16.f16.f32 "
        "{%0,%1,%2,%3}, {%4,%5,%6,%7}, {%8,%9}, {%0,%1,%2,%3};"
        : "+f"(c0), "+f"(c1), "+f"(c2), "+f"(c3)
        : "r"(a0), "r"(a1), "r"(a2), "r"(a3), "r"(b0), "r"(b1));
}

// k-pair permuted half index (LDS.64 -> fragment pairs)
__device__ __host__ __forceinline__ int sidx16(int k) {
    return ((k >> 4) << 4) | ((((k >> 1) & 3) << 2) | (((k >> 3) & 1) << 1) | (k & 1));
}

// ---------------- kernel A: init pooled buffer (uint4 fill) + LN coefficients ----------------
__global__ void k_init(int n4, const float* __restrict__ w1, const float* __restrict__ b1) {
    int i = blockIdx.x * blockDim.x + threadIdx.x;
    if (i < n4) {
        unsigned e = enc_f(NEG_FILL);
        ((uint4*)g_gf_enc)[i] = make_uint4(e, e, e, e);
    }
    if (blockIdx.x == 0 && threadIdx.x == 0) g_sum = 0.f;
    if (blockIdx.x == 0 && threadIdx.x < 44) {
        int t = threadIdx.x;
        float v = 0.f;
        if (t < 28) {
            int j = 0, k = 0, idx = t;
            #pragma unroll 1
            for (j = 0; j < 7; j++) { int len = 7 - j; if (idx < len) { k = j + idx; break; } idx -= len; }
            float s = 0.f;
            for (int e = 0; e < 64; e++) s = fmaf(w1[j*64+e], w1[k*64+e], s);
            v = (j == k) ? s : 2.0f * s;
        } else if (t < 35) {
            int j = t - 28;
            float s = 0.f;
            for (int e = 0; e < 64; e++) s = fmaf(b1[e], w1[j*64+e], s);
            v = 2.0f * s;
        } else if (t < 42) {
            int j = t - 35;
            float s = 0.f;
            for (int e = 0; e < 64; e++) s += w1[j*64+e];
            v = s * (1.0f/64.0f);
        } else if (t == 42) {
            float s = 0.f;
            for (int e = 0; e < 64; e++) s += b1[e];
            v = s * (1.0f/64.0f);
        } else {
            float s = 0.f;
            for (int e = 0; e < 64; e++) s = fmaf(b1[e], b1[e], s);
            v = s;
        }
        g_ln1[t] = v;
    }
}

// ---------------- k_main layout (R11 champion, unchanged) ----------------
#define TB 256
#define ROWS 128
#define AP_H 80              // halves per row; conflict-free fragment LDS.64
#define OFF_B    20480                 // A: 128*80*2
#define OFF_PARM (20480 + 20480)       // B: 128*80*2
#define PF_SBI   640
#define PF_XS    896
#define PF_CS    1664
#define SMEM_NEED (OFF_PARM + 2688 * 4)

__global__ __launch_bounds__(256, 2) void k_main(
    const float* __restrict__ muons, const int* __restrict__ bidx,
    const float* __restrict__ cond,
    const float* __restrict__ w1, const float* __restrict__ b1,
    const float* __restrict__ g1, const float* __restrict__ be1,
    const float* __restrict__ w2, const float* __restrict__ b2,
    const float* __restrict__ g2, const float* __restrict__ be2,
    int N, int nTiles)
{
    extern __shared__ char base[];
    __half* const Ah   = (__half*)(base);            // A operand (f16, k-permuted)
    __half* const Bh   = (__half*)(base + OFF_B);    // B operand (f16, k-permuted)
    float*  const PR   = (float*)(base + OFF_PARM);
    float* const B2s  = PR;            // 128
    float* const G2s  = B2s + 128;     // 128
    float* const BE2s = G2s + 128;     // 128
    float* const LNC  = BE2s + 128;    // 44 (+pad to 640)
    int*   const SBIb = (int*)(PR + PF_SBI);
    float* const Xsb  = PR + PF_XS;
    float* const Csb  = PR + PF_CS;

    const int tid  = threadIdx.x;
    const int lane = tid & 31;
    const int wrp  = tid >> 5;
    const int quad = lane >> 2;
    const int tig  = lane & 3;
    const int s16  = sidx16(lane);
    const int lr0  = wrp * 16;

    int*   const SBw = SBIb + wrp * 32;
    float* const Xw  = Xsb  + wrp * 96;
    float* const Cw  = Csb  + wrp * 128;
    const uint32_t xw_base  = smem_u32(Xw);
    const uint32_t sbw_base = smem_u32(SBw);

    // ---- per-lane constant layer1 params ----
    float w1a[7], w1b[7];
    #pragma unroll
    for (int j = 0; j < 7; j++) { w1a[j] = w1[j*64 + lane]; w1b[j] = w1[j*64 + lane + 32]; }
    const float b1a = b1[lane], b1b = b1[lane + 32];
    const float g1a = g1[lane], g1b = g1[lane + 32];
    const float e1a = be1[lane], e1b = be1[lane + 32];

    // ---- one-time smem: layer2 params + LN coeffs + B operand ----
    for (int i = tid; i < 128; i += TB) { B2s[i] = b2[i]; G2s[i] = g2[i]; BE2s[i] = be2[i]; }
    if (tid < 44) LNC[tid] = g_ln1[tid];
    for (int i = tid; i < 8192; i += TB) {
        int n = i & 127, k = i >> 7;
        Bh[n * AP_H + sidx16(k)] = __float2half_rn(w2[k * 128 + n]);
    }
    __syncthreads();

    // ---- per-warp prologue: fetch tile0's X/SB, gather cond ----
    {
        int rg = blockIdx.x * ROWS + lr0;
        if (lane < 12) {
            int gi = rg * 3 + lane * 4;
            cp_async16(xw_base + lane * 16, muons + gi, gi + 4 <= 3 * N);
        } else if (lane < 16) {
            int gi = rg + (lane - 12) * 4;
            cp_async16(sbw_base + (lane - 12) * 16, bidx + gi, gi + 4 <= N);
        }
        CP_COMMIT(); CP_WAIT0(); __syncwarp();
        if (lane < 16) {
            int r = rg + lane;
            int bi = (r < N) ? SBw[lane] : -1;
            SBw[lane] = bi;
            float4 c4 = (bi >= 0) ? *(const float4*)(cond + 4 * bi)
                                  : make_float4(0.f, 0.f, 0.f, 0.f);
            *(float4*)(Cw + lane * 4) = c4;
        }
        __syncwarp();
    }

    int it = 0;
    for (int tile = blockIdx.x; tile < nTiles; tile += gridDim.x, it ^= 1) {
        const int bufc = it, bufn = it ^ 1;
        const float* Xc  = Xw + bufc * 48;
        const float* Cc  = Cw + bufc * 64;
        const int*   SBc = SBw + bufc * 16;
        int*         SBn = SBw + bufn * 16;
        float*       Cn  = Cw + bufn * 64;

        const int  tnxt   = tile + gridDim.x;
        const bool vn     = tnxt < nTiles;
        const int  rg2    = tnxt * ROWS + lr0;

        // ---- per-warp prefetch of next tile's X/SB ----
        if (vn) {
            if (lane < 12) {
                int gi = rg2 * 3 + lane * 4;
                cp_async16(xw_base + (bufn * 48) * 4 + lane * 16, muons + gi, gi + 4 <= 3 * N);
            } else if (lane < 16) {
                int gi = rg2 + (lane - 12) * 4;
                cp_async16(sbw_base + (bufn * 16) * 4 + (lane - 12) * 16, bidx + gi, gi + 4 <= N);
            }
        }
        CP_COMMIT();

        // ---- event fast-path test ----
        const int ebi0  = SBc[0];
        const int ebi15 = SBc[15];
        const bool sfast = (ebi0 == ebi15) && (ebi0 >= 0);

        // ---- stage 1: layer1 (7->64) + closed-form LN(64) + lrelu -> A (f16) ----
        if (sfast) {
            const float4 cc = *(const float4*)(Cc);
            float base_a = b1a, base_b = b1b;
            base_a = fmaf(cc.x, w1a[3], base_a); base_b = fmaf(cc.x, w1b[3], base_b);
            base_a = fmaf(cc.y, w1a[4], base_a); base_b = fmaf(cc.y, w1b[4], base_b);
            base_a = fmaf(cc.z, w1a[5], base_a); base_b = fmaf(cc.z, w1b[5], base_b);
            base_a = fmaf(cc.w, w1a[6], base_a); base_b = fmaf(cc.w, w1b[6], base_b);
            float m_ev = LNC[42];
            m_ev = fmaf(cc.x, LNC[38], m_ev); m_ev = fmaf(cc.y, LNC[39], m_ev);
            m_ev = fmaf(cc.z, LNC[40], m_ev); m_ev = fmaf(cc.w, LNC[41], m_ev);
            const float mw0 = LNC[35], mw1 = LNC[36], mw2 = LNC[37];
            float l0 = LNC[28];
            l0 = fmaf(cc.x, LNC[3],  l0); l0 = fmaf(cc.y, LNC[4],  l0);
            l0 = fmaf(cc.z, LNC[5],  l0); l0 = fmaf(cc.w, LNC[6],  l0);
            float l1 = LNC[29];
            l1 = fmaf(cc.x, LNC[9],  l1); l1 = fmaf(cc.y, LNC[10], l1);
            l1 = fmaf(cc.z, LNC[11], l1); l1 = fmaf(cc.w, LNC[12], l1);
            float l2 = LNC[30];
            l2 = fmaf(cc.x, LNC[14], l2); l2 = fmaf(cc.y, LNC[15], l2);
            l2 = fmaf(cc.z, LNC[16], l2); l2 = fmaf(cc.w, LNC[17], l2);
            const float q00 = LNC[0], q01 = LNC[1], q02 = LNC[2];
            const float q11 = LNC[7], q12 = LNC[8], q22 = LNC[13];
            float q_ev = LNC[43];
            {
                float t3 = LNC[31];
                t3 = fmaf(cc.x, LNC[18], t3); t3 = fmaf(cc.y, LNC[19], t3);
                t3 = fmaf(cc.z, LNC[20], t3); t3 = fmaf(cc.w, LNC[21], t3);
                q_ev = fmaf(cc.x, t3, q_ev);
                float t4 = LNC[32];
                t4 = fmaf(cc.y, LNC[22], t4); t4 = fmaf(cc.z, LNC[23], t4);
                t4 = fmaf(cc.w, LNC[24], t4);
                q_ev = fmaf(cc.y, t4, q_ev);
                float t5 = LNC[33];
                t5 = fmaf(cc.z, LNC[25], t5); t5 = fmaf(cc.w, LNC[26], t5);
                q_ev = fmaf(cc.z, t5, q_ev);
                float t6 = fmaf(cc.w, LNC[27], LNC[34]);
                q_ev = fmaf(cc.w, t6, q_ev);
            }
            #pragma unroll 4
            for (int i = 0; i < 16; i++) {
                float x0 = Xc[i*3], x1 = Xc[i*3+1], x2 = Xc[i*3+2];
                float oa = fmaf(x2, w1a[2], fmaf(x1, w1a[1], fmaf(x0, w1a[0], base_a)));
                float ob = fmaf(x2, w1b[2], fmaf(x1, w1b[1], fmaf(x0, w1b[0], base_b)));
                float m  = fmaf(x2, mw2, fmaf(x1, mw1, fmaf(x0, mw0, m_ev)));
                float q  = q_ev;
                q = fmaf(x0, fmaf(x0, q00, l0), q);
                q = fmaf(x1, fmaf(x1, q11, fmaf(x0, q01, l1)), q);
                q = fmaf(x2, fmaf(x2, q22, fmaf(x1, q12, fmaf(x0, q02, l2))), q);
                float var  = fmaf(-m, m, q * (1.0f/64.0f));
                float rstd = rsqrtf(var + LN_EPS);
                float ha = lrelu(fmaf((oa - m) * rstd, g1a, e1a));
                float hb = lrelu(fmaf((ob - m) * rstd, g1b, e1b));
                Ah[(lr0 + i) * AP_H + s16]      = __float2half_rn(ha);
                Ah[(lr0 + i) * AP_H + s16 + 32] = __float2half_rn(hb);
            }
        } else {
            const int off7[7] = {0, 7, 13, 18, 22, 25, 27};
            #pragma unroll 2
            for (int i = 0; i < 16; i++) {
                float4 cc = *(const float4*)(Cc + i * 4);
                float z[7];
                z[0] = Xc[i*3]; z[1] = Xc[i*3+1]; z[2] = Xc[i*3+2];
                z[3] = cc.x; z[4] = cc.y; z[5] = cc.z; z[6] = cc.w;
                float oa = b1a, ob = b1b;
                #pragma unroll
                for (int j = 0; j < 7; j++) {
                    oa = fmaf(z[j], w1a[j], oa);
                    ob = fmaf(z[j], w1b[j], ob);
                }
                float m = LNC[42];
                #pragma unroll
                for (int j = 0; j < 7; j++) m = fmaf(z[j], LNC[35 + j], m);
                float q = LNC[43];
                #pragma unroll
                for (int j = 0; j < 7; j++) {
                    float t = LNC[28 + j];
                    #pragma unroll
                    for (int k = j; k < 7; k++) t = fmaf(z[k], LNC[off7[j] + k - j], t);
                    q = fmaf(z[j], t, q);
                }
                float var  = fmaf(-m, m, q * (1.0f/64.0f));
                float rstd = rsqrtf(var + LN_EPS);
                float ha = lrelu(fmaf((oa - m) * rstd, g1a, e1a));
                float hb = lrelu(fmaf((ob - m) * rstd, g1b, e1b));
                Ah[(lr0 + i) * AP_H + s16]      = __float2half_rn(ha);
                Ah[(lr0 + i) * AP_H + s16 + 32] = __float2half_rn(hb);
            }
        }
        __syncwarp();

        // ---- stage 2: GEMM 16x128x64 per warp via m16n8k16.f16 ----
        float acc[16][4];
        #pragma unroll
        for (int nt = 0; nt < 16; nt++)
            #pragma unroll
            for (int c = 0; c < 4; c++) acc[nt][c] = 0.f;

        const __half* ap0 = Ah + (lr0 + quad) * AP_H + tig * 4;
        const __half* ap1 = ap0 + 8 * AP_H;
        const __half* bp  = Bh + quad * AP_H + tig * 4;
        #pragma unroll
        for (int ks = 0; ks < 4; ks++) {
            uint2 A0 = *(const uint2*)(ap0 + ks * 16);
            uint2 A1 = *(const uint2*)(ap1 + ks * 16);
            #pragma unroll
            for (int nt = 0; nt < 16; nt++) {
                uint2 Bv = *(const uint2*)(bp + nt * 8 * AP_H + ks * 16);
                mma_f16(acc[nt][0], acc[nt][1], acc[nt][2], acc[nt][3],
                        A0.x, A1.x, A0.y, A1.y, Bv.x, Bv.y);
            }
        }

        // ---- wait prefetch; patch SB; launch next-tile cond gather ----
        CP_WAIT0(); __syncwarp();
        float4 c4n = make_float4(0.f, 0.f, 0.f, 0.f);
        int bin = -1;
        if (vn && lane < 16) {
            int r2 = rg2 + lane;
            bin = (r2 < N) ? SBn[lane] : -1;
            if (bin >= 0) c4n = *(const float4*)(cond + 4 * bin);
        }

        // ---- stage 3a: bias + LN(128) stats (quad-local) ----
        float sA = 0.f, qA = 0.f, sB = 0.f, qB = 0.f;
        #pragma unroll
        for (int nt = 0; nt < 16; nt++) {
            int col = nt * 8 + tig * 2;
            float2 bb = *(const float2*)(B2s + col);
            acc[nt][0] += bb.x; acc[nt][1] += bb.y;
            acc[nt][2] += bb.x; acc[nt][3] += bb.y;
            sA += acc[nt][0] + acc[nt][1];
            qA = fmaf(acc[nt][0], acc[nt][0], fmaf(acc[nt][1], acc[nt][1], qA));
            sB += acc[nt][2] + acc[nt][3];
            qB = fmaf(acc[nt][2], acc[nt][2], fmaf(acc[nt][3], acc[nt][3], qB));
        }
        #pragma unroll
        for (int d = 1; d <= 2; d <<= 1) {
            sA += __shfl_xor_sync(0xFFFFFFFFu, sA, d);
            qA += __shfl_xor_sync(0xFFFFFFFFu, qA, d);
            sB += __shfl_xor_sync(0xFFFFFFFFu, sB, d);
            qB += __shfl_xor_sync(0xFFFFFFFFu, qB, d);
        }
        float mA  = sA * (1.0f/128.0f);
        float rsA = rsqrtf(fmaf(-mA, mA, qA * (1.0f/128.0f)) + LN_EPS);
        float mB  = sB * (1.0f/128.0f);
        float rsB = rsqrtf(fmaf(-mB, mB, qB * (1.0f/128.0f)) + LN_EPS);

        // ---- stage 3b+3c: normalize + lrelu, pool + direct RED.MAX ----
        const int bi_ra = SBc[quad];
        const int bi_rb = SBc[quad + 8];
        unsigned* const gfast = g_gf_enc + (sfast ? ebi0 * 128 : 0);

        #pragma unroll
        for (int nt = 0; nt < 16; nt++) {
            int col = nt * 8 + tig * 2;
            float2 gg = *(const float2*)(G2s + col);
            float2 ee = *(const float2*)(BE2s + col);
            float v0 = lrelu(fmaf((acc[nt][0] - mA) * rsA, gg.x, ee.x));
            float v1 = lrelu(fmaf((acc[nt][1] - mA) * rsA, gg.y, ee.y));
            float v2 = lrelu(fmaf((acc[nt][2] - mB) * rsB, gg.x, ee.x));
            float v3 = lrelu(fmaf((acc[nt][3] - mB) * rsB, gg.y, ee.y));
            if (sfast) {
                float m0 = fmaxf(v0, v2), m1 = fmaxf(v1, v3);
                #pragma unroll
                for (int d = 4; d <= 16; d <<= 1) {
                    m0 = fmaxf(m0, __shfl_xor_sync(0xFFFFFFFFu, m0, d));
                    m1 = fmaxf(m1, __shfl_xor_sync(0xFFFFFFFFu, m1, d));
                }
                if (quad == (nt >> 1)) {
                    atomicMax(gfast + col,     enc_f(m0));
                    atomicMax(gfast + col + 1, enc_f(m1));
                }
            } else {
                if (bi_ra >= 0) {
                    atomicMax(&g_gf_enc[bi_ra * 128 + col],     enc_f(v0));
                    atomicMax(&g_gf_enc[bi_ra * 128 + col + 1], enc_f(v1));
                }
                if (bi_rb >= 0) {
                    atomicMax(&g_gf_enc[bi_rb * 128 + col],     enc_f(v2));
                    atomicMax(&g_gf_enc[bi_rb * 128 + col + 1], enc_f(v3));
                }
            }
        }

        if (vn && lane < 16) {
            SBn[lane] = bin;
            *(float4*)(Cn + lane * 4) = c4n;
        }
        __syncwarp();
    }
}

// ---------------- kernel C: decision net (+ |score| partial sums) ----------------
__global__ __launch_bounds__(256) void k_dec(
    const float* __restrict__ cond,
    const float* __restrict__ w3, const float* __restrict__ b3,
    const float* __restrict__ g3, const float* __restrict__ be3,
    const float* __restrict__ w4, const float* __restrict__ b4,
    const float* __restrict__ g4, const float* __restrict__ be4,
    const float* __restrict__ w5, const float* __restrict__ b5,
    int B)
{
    extern __shared__ float sm[];
    float* W3 = sm;
    float* W4 = W3 + 16896;
    float* W5 = W4 + 8192;
    float* B3 = W5 + 64;
    float* G3 = B3 + 128;
    float* BE3= G3 + 128;
    float* B4 = BE3 + 128;
    float* G4 = B4 + 64;
    float* BE4= G4 + 64;
    float* XB = BE4 + 64;

    const int tid = threadIdx.x, lane = tid & 31, wrp = tid >> 5;
    for (int i = tid; i < 16896; i += 256) W3[i] = w3[i];
    for (int i = tid; i < 8192;  i += 256) W4[i] = w4[i];
    for (int i = tid; i < 64;    i += 256) { W5[i] = w5[i]; B4[i] = b4[i]; G4[i] = g4[i]; BE4[i] = be4[i]; }
    for (int i = tid; i < 128;   i += 256) { B3[i] = b3[i]; G3[i] = g3[i]; BE3[i] = be3[i]; }
    __syncthreads();

    float* xb = XB + wrp * 136;
    const float b5v = b5[0];
    float absacc = 0.f;

    #pragma unroll 1
    for (int i = 0; i < 4; i++) {
        int row = (blockIdx.x * 8 + wrp) * 4 + i;
        if (row >= B) break;
        __syncwarp();
        #pragma unroll
        for (int j = 0; j < 4; j++)
            xb[lane + 32*j] = dec_f(g_gf_enc[row*128 + lane + 32*j]);
        if (lane < 4) xb[128 + lane] = cond[row*4 + lane];
        __syncwarp();

        float a0 = B3[lane], a1 = B3[lane+32], a2 = B3[lane+64], a3 = B3[lane+96];
        #pragma unroll 4
        for (int k = 0; k < 132; k++) {
            float xk = xb[k];
            const float* wr = W3 + k*128;
            a0 = fmaf(xk, wr[lane],      a0);
            a1 = fmaf(xk, wr[lane+32],   a1);
            a2 = fmaf(xk, wr[lane+64],   a2);
            a3 = fmaf(xk, wr[lane+96],   a3);
        }
        float s = a0+a1+a2+a3;
        float q = a0*a0 + a1*a1 + a2*a2 + a3*a3;
        #pragma unroll
        for (int d = 16; d; d >>= 1) {
            s += __shfl_xor_sync(0xFFFFFFFFu, s, d);
            q += __shfl_xor_sync(0xFFFFFFFFu, q, d);
        }
        float m = s * (1.0f/128.0f);
        float var = fmaf(-m, m, q * (1.0f/128.0f));
        float rs = rsqrtf(var + LN_EPS);
        a0 = lrelu(fmaf((a0-m)*rs, G3[lane],    BE3[lane]));
        a1 = lrelu(fmaf((a1-m)*rs, G3[lane+32], BE3[lane+32]));
        a2 = lrelu(fmaf((a2-m)*rs, G3[lane+64], BE3[lane+64]));
        a3 = lrelu(fmaf((a3-m)*rs, G3[lane+96], BE3[lane+96]));
        __syncwarp();
        xb[lane] = a0; xb[lane+32] = a1; xb[lane+64] = a2; xb[lane+96] = a3;
        __syncwarp();

        float c0v = B4[lane], c1v = B4[lane+32];
        #pragma unroll 4
        for (int k = 0; k < 128; k++) {
            float xk = xb[k];
            c0v = fmaf(xk, W4[k*64 + lane],      c0v);
            c1v = fmaf(xk, W4[k*64 + lane + 32], c1v);
        }
        s = c0v + c1v;
        q = c0v*c0v + c1v*c1v;
        #pragma unroll
        for (int d = 16; d; d >>= 1) {
            s += __shfl_xor_sync(0xFFFFFFFFu, s, d);
            q += __shfl_xor_sync(0xFFFFFFFFu, q, d);
        }
        m = s * (1.0f/64.0f);
        var = fmaf(-m, m, q * (1.0f/64.0f));
        rs = rsqrtf(var + LN_EPS);
        c0v = lrelu(fmaf((c0v-m)*rs, G4[lane],    BE4[lane]));
        c1v = lrelu(fmaf((c1v-m)*rs, G4[lane+32], BE4[lane+32]));

        float p = c0v * W5[lane] + c1v * W5[lane+32];
        #pragma unroll
        for (int d = 16; d; d >>= 1) p += __shfl_xor_sync(0xFFFFFFFFu, p, d);
        if (lane == 0) {
            float sc = p + b5v;
            g_score[row] = sc;
            absacc += fabsf(sc);
        }
    }
    if (lane == 0 && absacc != 0.f) atomicAdd(&g_sum, absacc);
}

// ---------------- kernel D: EMA normalize + tanh (parallel) ----------------
__global__ void k_final(float* __restrict__ out, int B) {
    float mean  = g_sum / (float)B;
    float ema   = 0.99f + 0.01f * mean;
    float denom = fmaxf(ema, 0.1f);
    int i = blockIdx.x * blockDim.x + threadIdx.x;
    if (i < B) {
        float sc = g_score[i] / denom;
        sc = fminf(fmaxf(sc, -5.0f), 5.0f);
        out[i] = 10.0f * tanhf(sc * 0.2f);
    }
}

// ---------------- launch ----------------
extern "C" void kernel_launch(void* const* d_in, const int* in_sizes, int n_in,
                              void* d_out, int out_size) {
    const float* muons = (const float*)d_in[0];
    const int*   bidx  = (const int*)  d_in[1];
    const float* cond  = (const float*)d_in[2];
    const float* w1  = (const float*)d_in[4];
    const float* b1  = (const float*)d_in[5];
    const float* g1  = (const float*)d_in[6];
    const float* be1 = (const float*)d_in[7];
    const float* w2  = (const float*)d_in[8];
    const float* b2  = (const float*)d_in[9];
    const float* g2  = (const float*)d_in[10];
    const float* be2 = (const float*)d_in[11];
    const float* w3  = (const float*)d_in[12];
    const float* b3  = (const float*)d_in[13];
    const float* g3  = (const float*)d_in[14];
    const float* be3 = (const float*)d_in[15];
    const float* w4  = (const float*)d_in[16];
    const float* b4  = (const float*)d_in[17];
    const float* g4  = (const float*)d_in[18];
    const float* be4 = (const float*)d_in[19];
    const float* w5  = (const float*)d_in[20];
    const float* b5  = (const float*)d_in[21];

    int N = in_sizes[0] / 3;
    int B = in_sizes[2] / 4;
    if (B > MAXB) B = MAXB;

    static const size_t SMEM_DEC = (size_t)(16896 + 8192 + 64 + 128*3 + 64*3 + 8*136) * 4;
    cudaFuncSetAttribute(k_main, cudaFuncAttributeMaxDynamicSharedMemorySize, (int)SMEM_NEED);
    cudaFuncSetAttribute(k_dec,  cudaFuncAttributeMaxDynamicSharedMemorySize, (int)SMEM_DEC);

    int initN4 = (B * 128) / 4;
    k_init<<<(initN4 + 255) / 256, 256>>>(initN4, w1, b1);

    int nTiles = (N + ROWS - 1) / ROWS;
    int nBlocks = 2 * 148;
    if (nBlocks > nTiles) nBlocks = nTiles;
    k_main<<<nBlocks, TB, SMEM_NEED>>>(muons, bidx, cond,
                                       w1, b1, g1, be1, w2, b2, g2, be2, N, nTiles);

    int decBlocks = (B + 31) / 32;
    k_dec<<<decBlocks, 256, SMEM_DEC>>>(cond, w3, b3, g3, be3,
                                        w4, b4, g4, be4, w5, b5, B);

    k_final<<<(B + 255) / 256, 256>>>((float*)d_out, B);
}

// round 17
// speedup vs baseline: 1.0430x; 1.0017x over previous
#include <cuda_runtime.h>
#include <cuda_fp16.h>
#include <math.h>
#include <cstdint>

#define LN_EPS 1e-5f
#define NEG_FILL -1.0e9f
#define MAXB 8192

// ---------------- device scratch ----------------
__device__ unsigned g_gf_enc[MAXB * 128];
__device__ float    g_score[MAXB];
__device__ float    g_ln1[44];   // closed-form LN(64) coefficients
__device__ float    g_sum;       // sum of |score| (accumulated by k_dec)

// ---------------- helpers ----------------
__device__ __forceinline__ unsigned enc_f(float f) {
    int i = __float_as_int(f);
    unsigned u = (unsigned)i;
    return (i < 0) ? ~u : (u | 0x80000000u);
}
__device__ __forceinline__ float dec_f(unsigned u) {
    return (u & 0x80000000u) ? __int_as_float((int)(u & 0x7FFFFFFFu))
                             : __int_as_float((int)(~u));
}
__device__ __forceinline__ float lrelu(float v) { return v >= 0.0f ? v : 0.2f * v; }
__device__ __forceinline__ uint32_t smem_u32(const void* p) {
    return (uint32_t)__cvta_generic_to_shared(p);
}
__device__ __forceinline__ void cp_async16(uint32_t dst, const void* src, bool full) {
    int sz = full ? 16 : 0;
    asm volatile("cp.async.cg.shared.global [%0], [%1], 16, %2;"
                 :: "r"(dst), "l"(src), "r"(sz));
}
#define CP_COMMIT() asm volatile("cp.async.commit_group;" ::: "memory")
#define CP_WAIT0()  asm volatile("cp.async.wait_group 0;" ::: "memory")

// fp16 warp MMA: D(16x8,f32) += A(16x16,f16) * B(16x8,f16)
__device__ __forceinline__ void mma_f16(float& c0, float& c1, float& c2, float& c3,
                                        uint32_t a0, uint32_t a1, uint32_t a2, uint32_t a3,
                                        uint32_t b0, uint32_t b1) {
    asm volatile(
        "mma.sync.aligned.m16n8k16.row.col.f32.f16.f16.f32 "
        "{%0,%1,%2,%3}, {%4,%5,%6,%7}, {%8,%9}, {%0,%1,%2,%3};"
        : "+f"(c0), "+f"(c1), "+f"(c2), "+f"(c3)
        : "r"(a0), "r"(a1), "r"(a2), "r"(a3), "r"(b0), "r"(b1));
}

// k-pair permuted half index (LDS.64 -> fragment pairs)
__device__ __host__ __forceinline__ int sidx16(int k) {
    return ((k >> 4) << 4) | ((((k >> 1) & 3) << 2) | (((k >> 3) & 1) << 1) | (k & 1));
}

// ---------------- kernel A: init pooled buffer (uint4 fill) + LN coefficients ----------------
__global__ void k_init(int n4, const float* __restrict__ w1, const float* __restrict__ b1) {
    int i = blockIdx.x * blockDim.x + threadIdx.x;
    if (i < n4) {
        unsigned e = enc_f(NEG_FILL);
        ((uint4*)g_gf_enc)[i] = make_uint4(e, e, e, e);
    }
    if (blockIdx.x == 0 && threadIdx.x == 0) g_sum = 0.f;
    if (blockIdx.x == 0 && threadIdx.x < 44) {
        int t = threadIdx.x;
        float v = 0.f;
        if (t < 28) {
            int j = 0, k = 0, idx = t;
            #pragma unroll 1
            for (j = 0; j < 7; j++) { int len = 7 - j; if (idx < len) { k = j + idx; break; } idx -= len; }
            float s = 0.f;
            for (int e = 0; e < 64; e++) s = fmaf(w1[j*64+e], w1[k*64+e], s);
            v = (j == k) ? s : 2.0f * s;
        } else if (t < 35) {
            int j = t - 28;
            float s = 0.f;
            for (int e = 0; e < 64; e++) s = fmaf(b1[e], w1[j*64+e], s);
            v = 2.0f * s;
        } else if (t < 42) {
            int j = t - 35;
            float s = 0.f;
            for (int e = 0; e < 64; e++) s += w1[j*64+e];
            v = s * (1.0f/64.0f);
        } else if (t == 42) {
            float s = 0.f;
            for (int e = 0; e < 64; e++) s += b1[e];
            v = s * (1.0f/64.0f);
        } else {
            float s = 0.f;
            for (int e = 0; e < 64; e++) s = fmaf(b1[e], b1[e], s);
            v = s;
        }
        g_ln1[t] = v;
    }
}

// ---------------- k_main layout (R11/R16 champion, unchanged) ----------------
#define TB 256
#define ROWS 128
#define AP_H 80              // halves per row; conflict-free fragment LDS.64
#define OFF_B    20480                 // A: 128*80*2
#define OFF_PARM (20480 + 20480)       // B: 128*80*2
#define PF_SBI   640
#define PF_XS    896
#define PF_CS    1664
#define SMEM_NEED (OFF_PARM + 2688 * 4)

__global__ __launch_bounds__(256, 2) void k_main(
    const float* __restrict__ muons, const int* __restrict__ bidx,
    const float* __restrict__ cond,
    const float* __restrict__ w1, const float* __restrict__ b1,
    const float* __restrict__ g1, const float* __restrict__ be1,
    const float* __restrict__ w2, const float* __restrict__ b2,
    const float* __restrict__ g2, const float* __restrict__ be2,
    int N, int nTiles)
{
    extern __shared__ char base[];
    __half* const Ah   = (__half*)(base);            // A operand (f16, k-permuted)
    __half* const Bh   = (__half*)(base + OFF_B);    // B operand (f16, k-permuted)
    float*  const PR   = (float*)(base + OFF_PARM);
    float* const B2s  = PR;            // 128
    float* const G2s  = B2s + 128;     // 128
    float* const BE2s = G2s + 128;     // 128
    float* const LNC  = BE2s + 128;    // 44 (+pad to 640)
    int*   const SBIb = (int*)(PR + PF_SBI);
    float* const Xsb  = PR + PF_XS;
    float* const Csb  = PR + PF_CS;

    const int tid  = threadIdx.x;
    const int lane = tid & 31;
    const int wrp  = tid >> 5;
    const int quad = lane >> 2;
    const int tig  = lane & 3;
    const int s16  = sidx16(lane);
    const int lr0  = wrp * 16;

    int*   const SBw = SBIb + wrp * 32;
    float* const Xw  = Xsb  + wrp * 96;
    float* const Cw  = Csb  + wrp * 128;
    const uint32_t xw_base  = smem_u32(Xw);
    const uint32_t sbw_base = smem_u32(SBw);

    // ---- per-lane constant layer1 params ----
    float w1a[7], w1b[7];
    #pragma unroll
    for (int j = 0; j < 7; j++) { w1a[j] = w1[j*64 + lane]; w1b[j] = w1[j*64 + lane + 32]; }
    const float b1a = b1[lane], b1b = b1[lane + 32];
    const float g1a = g1[lane], g1b = g1[lane + 32];
    const float e1a = be1[lane], e1b = be1[lane + 32];

    // ---- one-time smem: layer2 params + LN coeffs + B operand ----
    for (int i = tid; i < 128; i += TB) { B2s[i] = b2[i]; G2s[i] = g2[i]; BE2s[i] = be2[i]; }
    if (tid < 44) LNC[tid] = g_ln1[tid];
    for (int i = tid; i < 8192; i += TB) {
        int n = i & 127, k = i >> 7;
        Bh[n * AP_H + sidx16(k)] = __float2half_rn(w2[k * 128 + n]);
    }
    __syncthreads();

    // ---- per-warp prologue: fetch tile0's X/SB, gather cond ----
    {
        int rg = blockIdx.x * ROWS + lr0;
        if (lane < 12) {
            int gi = rg * 3 + lane * 4;
            cp_async16(xw_base + lane * 16, muons + gi, gi + 4 <= 3 * N);
        } else if (lane < 16) {
            int gi = rg + (lane - 12) * 4;
            cp_async16(sbw_base + (lane - 12) * 16, bidx + gi, gi + 4 <= N);
        }
        CP_COMMIT(); CP_WAIT0(); __syncwarp();
        if (lane < 16) {
            int r = rg + lane;
            int bi = (r < N) ? SBw[lane] : -1;
            SBw[lane] = bi;
            float4 c4 = (bi >= 0) ? *(const float4*)(cond + 4 * bi)
                                  : make_float4(0.f, 0.f, 0.f, 0.f);
            *(float4*)(Cw + lane * 4) = c4;
        }
        __syncwarp();
    }

    int it = 0;
    for (int tile = blockIdx.x; tile < nTiles; tile += gridDim.x, it ^= 1) {
        const int bufc = it, bufn = it ^ 1;
        const float* Xc  = Xw + bufc * 48;
        const float* Cc  = Cw + bufc * 64;
        const int*   SBc = SBw + bufc * 16;
        int*         SBn = SBw + bufn * 16;
        float*       Cn  = Cw + bufn * 64;

        const int  tnxt   = tile + gridDim.x;
        const bool vn     = tnxt < nTiles;
        const int  rg2    = tnxt * ROWS + lr0;

        // ---- per-warp prefetch of next tile's X/SB ----
        if (vn) {
            if (lane < 12) {
                int gi = rg2 * 3 + lane * 4;
                cp_async16(xw_base + (bufn * 48) * 4 + lane * 16, muons + gi, gi + 4 <= 3 * N);
            } else if (lane < 16) {
                int gi = rg2 + (lane - 12) * 4;
                cp_async16(sbw_base + (bufn * 16) * 4 + (lane - 12) * 16, bidx + gi, gi + 4 <= N);
            }
        }
        CP_COMMIT();

        // ---- event fast-path test ----
        const int ebi0  = SBc[0];
        const int ebi15 = SBc[15];
        const bool sfast = (ebi0 == ebi15) && (ebi0 >= 0);

        // ---- stage 1: layer1 (7->64) + closed-form LN(64) + lrelu -> A (f16) ----
        if (sfast) {
            const float4 cc = *(const float4*)(Cc);
            float base_a = b1a, base_b = b1b;
            base_a = fmaf(cc.x, w1a[3], base_a); base_b = fmaf(cc.x, w1b[3], base_b);
            base_a = fmaf(cc.y, w1a[4], base_a); base_b = fmaf(cc.y, w1b[4], base_b);
            base_a = fmaf(cc.z, w1a[5], base_a); base_b = fmaf(cc.z, w1b[5], base_b);
            base_a = fmaf(cc.w, w1a[6], base_a); base_b = fmaf(cc.w, w1b[6], base_b);
            float m_ev = LNC[42];
            m_ev = fmaf(cc.x, LNC[38], m_ev); m_ev = fmaf(cc.y, LNC[39], m_ev);
            m_ev = fmaf(cc.z, LNC[40], m_ev); m_ev = fmaf(cc.w, LNC[41], m_ev);
            const float mw0 = LNC[35], mw1 = LNC[36], mw2 = LNC[37];
            float l0 = LNC[28];
            l0 = fmaf(cc.x, LNC[3],  l0); l0 = fmaf(cc.y, LNC[4],  l0);
            l0 = fmaf(cc.z, LNC[5],  l0); l0 = fmaf(cc.w, LNC[6],  l0);
            float l1 = LNC[29];
            l1 = fmaf(cc.x, LNC[9],  l1); l1 = fmaf(cc.y, LNC[10], l1);
            l1 = fmaf(cc.z, LNC[11], l1); l1 = fmaf(cc.w, LNC[12], l1);
            float l2 = LNC[30];
            l2 = fmaf(cc.x, LNC[14], l2); l2 = fmaf(cc.y, LNC[15], l2);
            l2 = fmaf(cc.z, LNC[16], l2); l2 = fmaf(cc.w, LNC[17], l2);
            const float q00 = LNC[0], q01 = LNC[1], q02 = LNC[2];
            const float q11 = LNC[7], q12 = LNC[8], q22 = LNC[13];
            float q_ev = LNC[43];
            {
                float t3 = LNC[31];
                t3 = fmaf(cc.x, LNC[18], t3); t3 = fmaf(cc.y, LNC[19], t3);
                t3 = fmaf(cc.z, LNC[20], t3); t3 = fmaf(cc.w, LNC[21], t3);
                q_ev = fmaf(cc.x, t3, q_ev);
                float t4 = LNC[32];
                t4 = fmaf(cc.y, LNC[22], t4); t4 = fmaf(cc.z, LNC[23], t4);
                t4 = fmaf(cc.w, LNC[24], t4);
                q_ev = fmaf(cc.y, t4, q_ev);
                float t5 = LNC[33];
                t5 = fmaf(cc.z, LNC[25], t5); t5 = fmaf(cc.w, LNC[26], t5);
                q_ev = fmaf(cc.z, t5, q_ev);
                float t6 = fmaf(cc.w, LNC[27], LNC[34]);
                q_ev = fmaf(cc.w, t6, q_ev);
            }
            #pragma unroll 4
            for (int i = 0; i < 16; i++) {
                float x0 = Xc[i*3], x1 = Xc[i*3+1], x2 = Xc[i*3+2];
                float oa = fmaf(x2, w1a[2], fmaf(x1, w1a[1], fmaf(x0, w1a[0], base_a)));
                float ob = fmaf(x2, w1b[2], fmaf(x1, w1b[1], fmaf(x0, w1b[0], base_b)));
                float m  = fmaf(x2, mw2, fmaf(x1, mw1, fmaf(x0, mw0, m_ev)));
                float q  = q_ev;
                q = fmaf(x0, fmaf(x0, q00, l0), q);
                q = fmaf(x1, fmaf(x1, q11, fmaf(x0, q01, l1)), q);
                q = fmaf(x2, fmaf(x2, q22, fmaf(x1, q12, fmaf(x0, q02, l2))), q);
                float var  = fmaf(-m, m, q * (1.0f/64.0f));
                float rstd = rsqrtf(var + LN_EPS);
                float ha = lrelu(fmaf((oa - m) * rstd, g1a, e1a));
                float hb = lrelu(fmaf((ob - m) * rstd, g1b, e1b));
                Ah[(lr0 + i) * AP_H + s16]      = __float2half_rn(ha);
                Ah[(lr0 + i) * AP_H + s16 + 32] = __float2half_rn(hb);
            }
        } else {
            const int off7[7] = {0, 7, 13, 18, 22, 25, 27};
            #pragma unroll 2
            for (int i = 0; i < 16; i++) {
                float4 cc = *(const float4*)(Cc + i * 4);
                float z[7];
                z[0] = Xc[i*3]; z[1] = Xc[i*3+1]; z[2] = Xc[i*3+2];
                z[3] = cc.x; z[4] = cc.y; z[5] = cc.z; z[6] = cc.w;
                float oa = b1a, ob = b1b;
                #pragma unroll
                for (int j = 0; j < 7; j++) {
                    oa = fmaf(z[j], w1a[j], oa);
                    ob = fmaf(z[j], w1b[j], ob);
                }
                float m = LNC[42];
                #pragma unroll
                for (int j = 0; j < 7; j++) m = fmaf(z[j], LNC[35 + j], m);
                float q = LNC[43];
                #pragma unroll
                for (int j = 0; j < 7; j++) {
                    float t = LNC[28 + j];
                    #pragma unroll
                    for (int k = j; k < 7; k++) t = fmaf(z[k], LNC[off7[j] + k - j], t);
                    q = fmaf(z[j], t, q);
                }
                float var  = fmaf(-m, m, q * (1.0f/64.0f));
                float rstd = rsqrtf(var + LN_EPS);
                float ha = lrelu(fmaf((oa - m) * rstd, g1a, e1a));
                float hb = lrelu(fmaf((ob - m) * rstd, g1b, e1b));
                Ah[(lr0 + i) * AP_H + s16]      = __float2half_rn(ha);
                Ah[(lr0 + i) * AP_H + s16 + 32] = __float2half_rn(hb);
            }
        }
        __syncwarp();

        // ---- stage 2: GEMM 16x128x64 per warp via m16n8k16.f16 ----
        float acc[16][4];
        #pragma unroll
        for (int nt = 0; nt < 16; nt++)
            #pragma unroll
            for (int c = 0; c < 4; c++) acc[nt][c] = 0.f;

        const __half* ap0 = Ah + (lr0 + quad) * AP_H + tig * 4;
        const __half* ap1 = ap0 + 8 * AP_H;
        const __half* bp  = Bh + quad * AP_H + tig * 4;
        #pragma unroll
        for (int ks = 0; ks < 4; ks++) {
            uint2 A0 = *(const uint2*)(ap0 + ks * 16);
            uint2 A1 = *(const uint2*)(ap1 + ks * 16);
            #pragma unroll
            for (int nt = 0; nt < 16; nt++) {
                uint2 Bv = *(const uint2*)(bp + nt * 8 * AP_H + ks * 16);
                mma_f16(acc[nt][0], acc[nt][1], acc[nt][2], acc[nt][3],
                        A0.x, A1.x, A0.y, A1.y, Bv.x, Bv.y);
            }
        }

        // ---- wait prefetch; patch SB; launch next-tile cond gather ----
        CP_WAIT0(); __syncwarp();
        float4 c4n = make_float4(0.f, 0.f, 0.f, 0.f);
        int bin = -1;
        if (vn && lane < 16) {
            int r2 = rg2 + lane;
            bin = (r2 < N) ? SBn[lane] : -1;
            if (bin >= 0) c4n = *(const float4*)(cond + 4 * bin);
        }

        // ---- stage 3a: bias + LN(128) stats (quad-local) ----
        float sA = 0.f, qA = 0.f, sB = 0.f, qB = 0.f;
        #pragma unroll
        for (int nt = 0; nt < 16; nt++) {
            int col = nt * 8 + tig * 2;
            float2 bb = *(const float2*)(B2s + col);
            acc[nt][0] += bb.x; acc[nt][1] += bb.y;
            acc[nt][2] += bb.x; acc[nt][3] += bb.y;
            sA += acc[nt][0] + acc[nt][1];
            qA = fmaf(acc[nt][0], acc[nt][0], fmaf(acc[nt][1], acc[nt][1], qA));
            sB += acc[nt][2] + acc[nt][3];
            qB = fmaf(acc[nt][2], acc[nt][2], fmaf(acc[nt][3], acc[nt][3], qB));
        }
        #pragma unroll
        for (int d = 1; d <= 2; d <<= 1) {
            sA += __shfl_xor_sync(0xFFFFFFFFu, sA, d);
            qA += __shfl_xor_sync(0xFFFFFFFFu, qA, d);
            sB += __shfl_xor_sync(0xFFFFFFFFu, sB, d);
            qB += __shfl_xor_sync(0xFFFFFFFFu, qB, d);
        }
        float mA  = sA * (1.0f/128.0f);
        float rsA = rsqrtf(fmaf(-mA, mA, qA * (1.0f/128.0f)) + LN_EPS);
        float mB  = sB * (1.0f/128.0f);
        float rsB = rsqrtf(fmaf(-mB, mB, qB * (1.0f/128.0f)) + LN_EPS);

        // ---- stage 3b+3c: normalize + lrelu, pool + direct RED.MAX ----
        const int bi_ra = SBc[quad];
        const int bi_rb = SBc[quad + 8];
        unsigned* const gfast = g_gf_enc + (sfast ? ebi0 * 128 : 0);

        #pragma unroll
        for (int nt = 0; nt < 16; nt++) {
            int col = nt * 8 + tig * 2;
            float2 gg = *(const float2*)(G2s + col);
            float2 ee = *(const float2*)(BE2s + col);
            float v0 = lrelu(fmaf((acc[nt][0] - mA) * rsA, gg.x, ee.x));
            float v1 = lrelu(fmaf((acc[nt][1] - mA) * rsA, gg.y, ee.y));
            float v2 = lrelu(fmaf((acc[nt][2] - mB) * rsB, gg.x, ee.x));
            float v3 = lrelu(fmaf((acc[nt][3] - mB) * rsB, gg.y, ee.y));
            if (sfast) {
                float m0 = fmaxf(v0, v2), m1 = fmaxf(v1, v3);
                #pragma unroll
                for (int d = 4; d <= 16; d <<= 1) {
                    m0 = fmaxf(m0, __shfl_xor_sync(0xFFFFFFFFu, m0, d));
                    m1 = fmaxf(m1, __shfl_xor_sync(0xFFFFFFFFu, m1, d));
                }
                if (quad == (nt >> 1)) {
                    atomicMax(gfast + col,     enc_f(m0));
                    atomicMax(gfast + col + 1, enc_f(m1));
                }
            } else {
                if (bi_ra >= 0) {
                    atomicMax(&g_gf_enc[bi_ra * 128 + col],     enc_f(v0));
                    atomicMax(&g_gf_enc[bi_ra * 128 + col + 1], enc_f(v1));
                }
                if (bi_rb >= 0) {
                    atomicMax(&g_gf_enc[bi_rb * 128 + col],     enc_f(v2));
                    atomicMax(&g_gf_enc[bi_rb * 128 + col + 1], enc_f(v3));
                }
            }
        }

        if (vn && lane < 16) {
            SBn[lane] = bin;
            *(float4*)(Cn + lane * 4) = c4n;
        }
        __syncwarp();
    }
}

// ---------------- kernel C: decision net (float4 weight loads) ----------------
__global__ __launch_bounds__(256) void k_dec(
    const float* __restrict__ cond,
    const float* __restrict__ w3, const float* __restrict__ b3,
    const float* __restrict__ g3, const float* __restrict__ be3,
    const float* __restrict__ w4, const float* __restrict__ b4,
    const float* __restrict__ g4, const float* __restrict__ be4,
    const float* __restrict__ w5, const float* __restrict__ b5,
    int B)
{
    extern __shared__ float sm[];
    float* W3 = sm;
    float* W4 = W3 + 16896;
    float* W5 = W4 + 8192;
    float* B3 = W5 + 64;
    float* G3 = B3 + 128;
    float* BE3= G3 + 128;
    float* B4 = BE3 + 128;
    float* G4 = B4 + 64;
    float* BE4= G4 + 64;
    float* XB = BE4 + 64;

    const int tid = threadIdx.x, lane = tid & 31, wrp = tid >> 5;
    {
        const float4* w34 = (const float4*)w3;
        float4*       W34 = (float4*)W3;
        for (int i = tid; i < 4224; i += 256) W34[i] = w34[i];   // 16896 floats
        const float4* w44 = (const float4*)w4;
        float4*       W44 = (float4*)W4;
        for (int i = tid; i < 2048; i += 256) W44[i] = w44[i];   // 8192 floats
    }
    for (int i = tid; i < 64;  i += 256) { W5[i] = w5[i]; B4[i] = b4[i]; G4[i] = g4[i]; BE4[i] = be4[i]; }
    for (int i = tid; i < 128; i += 256) { B3[i] = b3[i]; G3[i] = g3[i]; BE3[i] = be3[i]; }
    __syncthreads();

    float* xb = XB + wrp * 136;
    const float b5v = b5[0];
    float absacc = 0.f;

    #pragma unroll 1
    for (int i = 0; i < 4; i++) {
        int row = (blockIdx.x * 8 + wrp) * 4 + i;
        if (row >= B) break;
        __syncwarp();
        #pragma unroll
        for (int j = 0; j < 4; j++)
            xb[lane + 32*j] = dec_f(g_gf_enc[row*128 + lane + 32*j]);
        if (lane < 4) xb[128 + lane] = cond[row*4 + lane];
        __syncwarp();

        float a0 = B3[lane], a1 = B3[lane+32], a2 = B3[lane+64], a3 = B3[lane+96];
        #pragma unroll 4
        for (int k = 0; k < 132; k++) {
            float xk = xb[k];
            const float* wr = W3 + k*128;
            a0 = fmaf(xk, wr[lane],      a0);
            a1 = fmaf(xk, wr[lane+32],   a1);
            a2 = fmaf(xk, wr[lane+64],   a2);
            a3 = fmaf(xk, wr[lane+96],   a3);
        }
        float s = a0+a1+a2+a3;
        float q = a0*a0 + a1*a1 + a2*a2 + a3*a3;
        #pragma unroll
        for (int d = 16; d; d >>= 1) {
            s += __shfl_xor_sync(0xFFFFFFFFu, s, d);
            q += __shfl_xor_sync(0xFFFFFFFFu, q, d);
        }
        float m = s * (1.0f/128.0f);
        float var = fmaf(-m, m, q * (1.0f/128.0f));
        float rs = rsqrtf(var + LN_EPS);
        a0 = lrelu(fmaf((a0-m)*rs, G3[lane],    BE3[lane]));
        a1 = lrelu(fmaf((a1-m)*rs, G3[lane+32], BE3[lane+32]));
        a2 = lrelu(fmaf((a2-m)*rs, G3[lane+64], BE3[lane+64]));
        a3 = lrelu(fmaf((a3-m)*rs, G3[lane+96], BE3[lane+96]));
        __syncwarp();
        xb[lane] = a0; xb[lane+32] = a1; xb[lane+64] = a2; xb[lane+96] = a3;
        __syncwarp();

        float c0v = B4[lane], c1v = B4[lane+32];
        #pragma unroll 4
        for (int k = 0; k < 128; k++) {
            float xk = xb[k];
            c0v = fmaf(xk, W4[k*64 + lane],      c0v);
            c1v = fmaf(xk, W4[k*64 + lane + 32], c1v);
        }
        s = c0v + c1v;
        q = c0v*c0v + c1v*c1v;
        #pragma unroll
        for (int d = 16; d; d >>= 1) {
            s += __shfl_xor_sync(0xFFFFFFFFu, s, d);
            q += __shfl_xor_sync(0xFFFFFFFFu, q, d);
        }
        m = s * (1.0f/64.0f);
        var = fmaf(-m, m, q * (1.0f/64.0f));
        rs = rsqrtf(var + LN_EPS);
        c0v = lrelu(fmaf((c0v-m)*rs, G4[lane],    BE4[lane]));
        c1v = lrelu(fmaf((c1v-m)*rs, G4[lane+32], BE4[lane+32]));

        float p = c0v * W5[lane] + c1v * W5[lane+32];
        #pragma unroll
        for (int d = 16; d; d >>= 1) p += __shfl_xor_sync(0xFFFFFFFFu, p, d);
        if (lane == 0) {
            float sc = p + b5v;
            g_score[row] = sc;
            absacc += fabsf(sc);
        }
    }
    if (lane == 0 && absacc != 0.f) atomicAdd(&g_sum, absacc);
}

// ---------------- kernel D: EMA normalize + tanh (parallel) ----------------
__global__ void k_final(float* __restrict__ out, int B) {
    float mean  = g_sum / (float)B;
    float ema   = 0.99f + 0.01f * mean;
    float denom = fmaxf(ema, 0.1f);
    int i = blockIdx.x * blockDim.x + threadIdx.x;
    if (i < B) {
        float sc = g_score[i] / denom;
        sc = fminf(fmaxf(sc, -5.0f), 5.0f);
        out[i] = 10.0f * tanhf(sc * 0.2f);
    }
}

// ---------------- launch ----------------
extern "C" void kernel_launch(void* const* d_in, const int* in_sizes, int n_in,
                              void* d_out, int out_size) {
    const float* muons = (const float*)d_in[0];
    const int*   bidx  = (const int*)  d_in[1];
    const float* cond  = (const float*)d_in[2];
    const float* w1  = (const float*)d_in[4];
    const float* b1  = (const float*)d_in[5];
    const float* g1  = (const float*)d_in[6];
    const float* be1 = (const float*)d_in[7];
    const float* w2  = (const float*)d_in[8];
    const float* b2  = (const float*)d_in[9];
    const float* g2  = (const float*)d_in[10];
    const float* be2 = (const float*)d_in[11];
    const float* w3  = (const float*)d_in[12];
    const float* b3  = (const float*)d_in[13];
    const float* g3  = (const float*)d_in[14];
    const float* be3 = (const float*)d_in[15];
    const float* w4  = (const float*)d_in[16];
    const float* b4  = (const float*)d_in[17];
    const float* g4  = (const float*)d_in[18];
    const float* be4 = (const float*)d_in[19];
    const float* w5  = (const float*)d_in[20];
    const float* b5  = (const float*)d_in[21];

    int N = in_sizes[0] / 3;
    int B = in_sizes[2] / 4;
    if (B > MAXB) B = MAXB;

    static const size_t SMEM_DEC = (size_t)(16896 + 8192 + 64 + 128*3 + 64*3 + 8*136) * 4;
    cudaFuncSetAttribute(k_main, cudaFuncAttributeMaxDynamicSharedMemorySize, (int)SMEM_NEED);
    cudaFuncSetAttribute(k_dec,  cudaFuncAttributeMaxDynamicSharedMemorySize, (int)SMEM_DEC);

    int initN4 = (B * 128) / 4;
    k_init<<<(initN4 + 255) / 256, 256>>>(initN4, w1, b1);

    int nTiles = (N + ROWS - 1) / ROWS;
    int nBlocks = 2 * 148;
    if (nBlocks > nTiles) nBlocks = nTiles;
    k_main<<<nBlocks, TB, SMEM_NEED>>>(muons, bidx, cond,
                                       w1, b1, g1, be1, w2, b2, g2, be2, N, nTiles);

    int decBlocks = (B + 31) / 32;
    k_dec<<<decBlocks, 256, SMEM_DEC>>>(cond, w3, b3, g3, be3,
                                        w4, b4, g4, be4, w5, b5, B);

    k_final<<<(B + 255) / 256, 256>>>((float*)d_out, B);
}